// round 1
// baseline (speedup 1.0000x reference)
#include <cuda_runtime.h>

#define BB   256
#define NN   1152
#define OO   10
#define IL   8
#define OL   16
#define JJ   160              // OO * OL
#define EPSF 1e-7f

// ---- scratch (static device globals; no allocation) ----
__device__ float g_uhat[(size_t)BB * NN * JJ];   // 189 MB, layout [b][n][j], j = o*16+k
__device__ float g_s0[BB * JJ];
__device__ float g_v[BB * JJ];
__device__ float g_b1[(size_t)BB * NN * OO];     // 11.8 MB routing logits after iter-0

// ---------------------------------------------------------------------------
__global__ void k_zero() {
    int i = blockIdx.x * blockDim.x + threadIdx.x;
    if (i < BB * JJ) g_s0[i] = 0.f;
}

// ---------------------------------------------------------------------------
// u_hat + iter-0 partial sums.  grid (144, 8) = (n-blocks of 8, b-blocks of 32),
// block 160 threads (thread = j).  W held in registers (64/thread), x staged in smem.
__global__ void k_uhat(const float* __restrict__ x, const float* __restrict__ w) {
    const int j  = threadIdx.x;
    const int n0 = blockIdx.x * 8;
    const int b0 = blockIdx.y * 32;

    __shared__ __align__(16) float x_sm[32 * 64];   // [bb][n*8+i]
    for (int idx = j; idx < 32 * 64; idx += 160) {
        int bb = idx >> 6, q = idx & 63;
        x_sm[idx] = x[(size_t)(b0 + bb) * (NN * IL) + n0 * IL + q];
    }

    float Wr[8][8];
    {
        const int wb = (j >> 4) * 128 + (j & 15);   // o*128 + k
        #pragma unroll
        for (int n = 0; n < 8; n++)
            #pragma unroll
            for (int i = 0; i < 8; i++)
                Wr[n][i] = w[(size_t)(n0 + n) * 1280 + wb + i * 16];
    }
    __syncthreads();

    for (int bb = 0; bb < 32; bb++) {
        float acc = 0.f;
        float* outp = &g_uhat[((size_t)(b0 + bb) * NN + n0) * JJ + j];
        #pragma unroll
        for (int n = 0; n < 8; n++) {
            const float4* xv = reinterpret_cast<const float4*>(&x_sm[bb * 64 + n * 8]);
            float4 xa = xv[0], xb = xv[1];
            float u = Wr[n][0] * xa.x + Wr[n][1] * xa.y + Wr[n][2] * xa.z + Wr[n][3] * xa.w
                    + Wr[n][4] * xb.x + Wr[n][5] * xb.y + Wr[n][6] * xb.z + Wr[n][7] * xb.w;
            outp[n * JJ] = u;     // 160 threads -> 640B contiguous per (b,n)
            acc += u;
        }
        atomicAdd(&g_s0[(b0 + bb) * JJ + j], acc);
    }
}

// ---------------------------------------------------------------------------
// iter-0 squash: v0 = squash(0.1 * sum + bias).  grid 256 (b), block 160 (j).
__global__ void k_squash0(const float* __restrict__ bias) {
    const int b = blockIdx.x, j = threadIdx.x;
    float s = 0.1f * g_s0[b * JJ + j] + bias[j];
    float d = s * s;
    #pragma unroll
    for (int msk = 1; msk < 16; msk <<= 1)
        d += __shfl_xor_sync(0xffffffffu, d, msk, 16);
    g_v[b * JJ + j] = s * (d / ((1.f + d) * sqrtf(d + EPSF)));
}

// ---------------------------------------------------------------------------
// One routing iteration fused: agreement dot + softmax + weighted sum + squash.
// grid 256 (b), block 256 (8 warps, warp w owns n in [w*144, w*144+144)).
// Lane l holds j = l + 32m for m=0..4;  o = 2m + (l>=16), k = l&15.
template <int LAST>
__global__ void k_route(const float* __restrict__ bias, float* __restrict__ vout) {
    const int b   = blockIdx.x;
    const int tid = threadIdx.x;
    const int wp  = tid >> 5, l = tid & 31;
    const int h16 = l & 16;                 // 0 (even o) or 16 (odd o)
    const unsigned FULL = 0xffffffffu;

    float vv[5], sacc[5];
    #pragma unroll
    for (int m = 0; m < 5; m++) { vv[m] = g_v[b * JJ + l + 32 * m]; sacc[m] = 0.f; }

    const int nbeg = wp * 144, nend = nbeg + 144;
    #pragma unroll 2
    for (int n = nbeg; n < nend; n++) {
        const size_t ub = ((size_t)b * NN + n) * JJ + l;
        float u[5], p[5];
        #pragma unroll
        for (int m = 0; m < 5; m++) u[m] = g_uhat[ub + 32 * m];
        #pragma unroll
        for (int m = 0; m < 5; m++) p[m] = u[m] * vv[m];
        // reduce over the 16 k-lanes -> agreement dot per o (replicated in half)
        #pragma unroll
        for (int m = 0; m < 5; m++) {
            #pragma unroll
            for (int msk = 1; msk < 16; msk <<= 1)
                p[m] += __shfl_xor_sync(FULL, p[m], msk, 16);
        }

        float bn[5];
        if (LAST) {
            const float* bp = &g_b1[((size_t)b * NN + n) * OO];
            #pragma unroll
            for (int m = 0; m < 5; m++) bn[m] = p[m] + bp[2 * m + (h16 >> 4)];
        } else {
            #pragma unroll
            for (int m = 0; m < 5; m++) bn[m] = p[m];
            if (l == 0 || l == 16) {
                float* bp = &g_b1[((size_t)b * NN + n) * OO];
                #pragma unroll
                for (int m = 0; m < 5; m++) bp[2 * m + (h16 >> 4)] = bn[m];
            }
        }

        // softmax over O=10 without max-sub (|bn| < ~2).  Only lanes {0..4,16..20}
        // compute a useful exp; broadcast via shfl.
        const int s5 = l & 15;
        float bsel = bn[4];
        bsel = (s5 == 0) ? bn[0] : bsel;
        bsel = (s5 == 1) ? bn[1] : bsel;
        bsel = (s5 == 2) ? bn[2] : bsel;
        bsel = (s5 == 3) ? bn[3] : bsel;
        float e = __expf(bsel);
        float c[5];
        #pragma unroll
        for (int m = 0; m < 5; m++) c[m] = __shfl_sync(FULL, e, h16 + m);
        float tot = c[0] + c[1] + c[2] + c[3] + c[4];
        tot += __shfl_xor_sync(FULL, tot, 16);
        float inv = 1.f / tot;
        #pragma unroll
        for (int m = 0; m < 5; m++) sacc[m] += (c[m] * inv) * u[m];
    }

    // block reduce over 8 warps, then fused squash (block owns b exclusively)
    __shared__ float s_sm[8][JJ];
    #pragma unroll
    for (int m = 0; m < 5; m++) s_sm[wp][l + 32 * m] = sacc[m];
    __syncthreads();

    if (tid < JJ) {
        float s = bias[tid];
        #pragma unroll
        for (int w8 = 0; w8 < 8; w8++) s += s_sm[w8][tid];
        float d = s * s;
        #pragma unroll
        for (int msk = 1; msk < 16; msk <<= 1)
            d += __shfl_xor_sync(FULL, d, msk, 16);
        float res = s * (d / ((1.f + d) * sqrtf(d + EPSF)));
        if (LAST) vout[b * JJ + tid] = res;
        else      g_v[b * JJ + tid]  = res;
    }
}

// ---------------------------------------------------------------------------
extern "C" void kernel_launch(void* const* d_in, const int* in_sizes, int n_in,
                              void* d_out, int out_size) {
    const float* x    = (const float*)d_in[0];   // (256,1152,8,1)
    const float* w    = (const float*)d_in[1];   // (1,1152,10,8,16)
    const float* bias = (const float*)d_in[2];   // (1,1,10,16,1)
    float* out = (float*)d_out;                  // (256,1,10,16,1)

    k_zero<<<40, 1024>>>();
    k_uhat<<<dim3(144, 8), 160>>>(x, w);
    k_squash0<<<256, 160>>>(bias);
    k_route<0><<<256, 256>>>(bias, nullptr);     // iter 1 -> v1, b1
    k_route<1><<<256, 256>>>(bias, out);         // iter 2 -> output
}

// round 2
// speedup vs baseline: 1.3826x; 1.3826x over previous
#include <cuda_runtime.h>

#define BB   256
#define NN   1152
#define OO   10
#define IL   8
#define OL   16
#define JJ   160              // OO * OL
#define EPSF 1e-7f
#define NPART 8               // n-partitions per b in k_route
#define NPERW 18              // 1152 / (NPART*8 warps)

// ---- scratch (static device globals; no allocation) ----
__device__ float g_uhat[(size_t)BB * NN * JJ];     // 189 MB, [b][n][j], j = o*16+k
__device__ float g_part[144 * BB * JJ];            // 23.6 MB k_uhat partial sums [nblk][b][j]
__device__ float g_sA[BB * JJ];                    // route iter-1 s accumulator
__device__ float g_sB[BB * JJ];                    // route iter-2 s accumulator
__device__ float g_v[BB * JJ];
__device__ float g_b1[(size_t)BB * NN * OO];       // 11.8 MB routing logits after iter-0

// ---------------------------------------------------------------------------
__global__ void k_zero() {
    int i = blockIdx.x * blockDim.x + threadIdx.x;
    if (i < BB * JJ) { g_sA[i] = 0.f; g_sB[i] = 0.f; }
}

// ---------------------------------------------------------------------------
// u_hat + iter-0 partial sums.  grid (144, 8) = (n-blocks of 8, b-blocks of 32),
// block 160 threads (thread = j).  W in registers (64/thread), x staged in smem.
// Partials written to g_part (no atomics).
__global__ void k_uhat(const float* __restrict__ x, const float* __restrict__ w) {
    const int j  = threadIdx.x;
    const int n0 = blockIdx.x * 8;
    const int b0 = blockIdx.y * 32;

    __shared__ __align__(16) float x_sm[32 * 64];   // [bb][n*8+i]
    for (int idx = j; idx < 32 * 64; idx += 160) {
        int bb = idx >> 6, q = idx & 63;
        x_sm[idx] = x[(size_t)(b0 + bb) * (NN * IL) + n0 * IL + q];
    }

    float Wr[8][8];
    {
        const int wb = (j >> 4) * 128 + (j & 15);   // o*128 + k
        #pragma unroll
        for (int n = 0; n < 8; n++)
            #pragma unroll
            for (int i = 0; i < 8; i++)
                Wr[n][i] = w[(size_t)(n0 + n) * 1280 + wb + i * 16];
    }
    __syncthreads();

    for (int bb = 0; bb < 32; bb++) {
        float acc = 0.f;
        float* outp = &g_uhat[((size_t)(b0 + bb) * NN + n0) * JJ + j];
        #pragma unroll
        for (int n = 0; n < 8; n++) {
            const float4* xv = reinterpret_cast<const float4*>(&x_sm[bb * 64 + n * 8]);
            float4 xa = xv[0], xb = xv[1];
            float u = Wr[n][0] * xa.x + Wr[n][1] * xa.y + Wr[n][2] * xa.z + Wr[n][3] * xa.w
                    + Wr[n][4] * xb.x + Wr[n][5] * xb.y + Wr[n][6] * xb.z + Wr[n][7] * xb.w;
            outp[n * JJ] = u;     // 160 threads -> 640B contiguous per (b,n)
            acc += u;
        }
        g_part[((size_t)blockIdx.x * BB + (b0 + bb)) * JJ + j] = acc;
    }
}

// ---------------------------------------------------------------------------
// iter-0: reduce k_uhat partials, s0 = 0.1*sum + bias, squash -> g_v.
__global__ void k_squash0(const float* __restrict__ bias) {
    const int b = blockIdx.x, j = threadIdx.x;
    float s = 0.f;
    #pragma unroll 4
    for (int nb = 0; nb < 144; nb++)
        s += g_part[((size_t)nb * BB + b) * JJ + j];
    s = 0.1f * s + bias[j];
    float d = s * s;
    #pragma unroll
    for (int msk = 1; msk < 16; msk <<= 1)
        d += __shfl_xor_sync(0xffffffffu, d, msk, 16);
    g_v[b * JJ + j] = s * (d / ((1.f + d) * sqrtf(d + EPSF)));
}

// ---------------------------------------------------------------------------
// Generic: s -> squash -> dst
__global__ void k_squash(const float* __restrict__ sbuf, const float* __restrict__ bias,
                         float* __restrict__ dst) {
    const int b = blockIdx.x, j = threadIdx.x;
    float s = sbuf[b * JJ + j] + bias[j];
    float d = s * s;
    #pragma unroll
    for (int msk = 1; msk < 16; msk <<= 1)
        d += __shfl_xor_sync(0xffffffffu, d, msk, 16);
    dst[b * JJ + j] = s * (d / ((1.f + d) * sqrtf(d + EPSF)));
}

// ---------------------------------------------------------------------------
// One routing iteration: agreement dot + softmax + weighted partial sum.
// grid (256 b, NPART), block 256 (8 warps); warp handles NPERW n values.
// Lane l holds j = l + 32m, m=0..4;  o = 2m + (l>=16), k = l&15.
template <int LAST>
__global__ void k_route(float* __restrict__ sbuf) {
    const int b   = blockIdx.x;
    const int tid = threadIdx.x;
    const int wp  = tid >> 5, l = tid & 31;
    const int h16 = l & 16;                 // 0 (even o) or 16 (odd o)
    const unsigned FULL = 0xffffffffu;

    float vv[5], sacc[5];
    #pragma unroll
    for (int m = 0; m < 5; m++) { vv[m] = g_v[b * JJ + l + 32 * m]; sacc[m] = 0.f; }

    const int nbeg = (blockIdx.y * 8 + wp) * NPERW;
    #pragma unroll 2
    for (int nn = 0; nn < NPERW; nn++) {
        const int n = nbeg + nn;
        const size_t ub = ((size_t)b * NN + n) * JJ + l;
        float u[5], p[5];
        #pragma unroll
        for (int m = 0; m < 5; m++) u[m] = g_uhat[ub + 32 * m];
        #pragma unroll
        for (int m = 0; m < 5; m++) p[m] = u[m] * vv[m];
        // reduce over the 16 k-lanes -> agreement dot per o (replicated in half)
        #pragma unroll
        for (int m = 0; m < 5; m++) {
            #pragma unroll
            for (int msk = 1; msk < 16; msk <<= 1)
                p[m] += __shfl_xor_sync(FULL, p[m], msk, 16);
        }

        float bn[5];
        if (LAST) {
            const float* bp = &g_b1[((size_t)b * NN + n) * OO];
            #pragma unroll
            for (int m = 0; m < 5; m++) bn[m] = p[m] + bp[2 * m + (h16 >> 4)];
        } else {
            #pragma unroll
            for (int m = 0; m < 5; m++) bn[m] = p[m];
            if (l == 0 || l == 16) {
                float* bp = &g_b1[((size_t)b * NN + n) * OO];
                #pragma unroll
                for (int m = 0; m < 5; m++) bp[2 * m + (h16 >> 4)] = bn[m];
            }
        }

        // softmax over O=10 without max-sub (|bn| < ~2).  Lanes {0..4,16..20}
        // compute the exp; broadcast via shfl.
        const int s5 = l & 15;
        float bsel = bn[4];
        bsel = (s5 == 0) ? bn[0] : bsel;
        bsel = (s5 == 1) ? bn[1] : bsel;
        bsel = (s5 == 2) ? bn[2] : bsel;
        bsel = (s5 == 3) ? bn[3] : bsel;
        float e = __expf(bsel);
        float c[5];
        #pragma unroll
        for (int m = 0; m < 5; m++) c[m] = __shfl_sync(FULL, e, h16 + m);
        float tot = c[0] + c[1] + c[2] + c[3] + c[4];
        tot += __shfl_xor_sync(FULL, tot, 16);
        float inv = 1.f / tot;
        #pragma unroll
        for (int m = 0; m < 5; m++) sacc[m] += (c[m] * inv) * u[m];
    }

    // block reduce over 8 warps, then one atomic per (b,j) into sbuf
    __shared__ float s_sm[8][JJ];
    #pragma unroll
    for (int m = 0; m < 5; m++) s_sm[wp][l + 32 * m] = sacc[m];
    __syncthreads();

    if (tid < JJ) {
        float s = 0.f;
        #pragma unroll
        for (int w8 = 0; w8 < 8; w8++) s += s_sm[w8][tid];
        atomicAdd(&sbuf[b * JJ + tid], s);
    }
}

// ---------------------------------------------------------------------------
extern "C" void kernel_launch(void* const* d_in, const int* in_sizes, int n_in,
                              void* d_out, int out_size) {
    const float* x    = (const float*)d_in[0];   // (256,1152,8,1)
    const float* w    = (const float*)d_in[1];   // (1,1152,10,8,16)
    const float* bias = (const float*)d_in[2];   // (1,1,10,16,1)
    float* out = (float*)d_out;                  // (256,1,10,16,1)

    float* sA; cudaGetSymbolAddress((void**)&sA, g_sA);
    float* sB; cudaGetSymbolAddress((void**)&sB, g_sB);
    float* v;  cudaGetSymbolAddress((void**)&v,  g_v);

    k_zero<<<40, 1024>>>();
    k_uhat<<<dim3(144, 8), 160>>>(x, w);
    k_squash0<<<256, 160>>>(bias);                    // v0
    k_route<0><<<dim3(256, NPART), 256>>>(sA);        // iter 1 partials + b1
    k_squash<<<256, 160>>>(sA, bias, v);              // v1
    k_route<1><<<dim3(256, NPART), 256>>>(sB);        // iter 2 partials
    k_squash<<<256, 160>>>(sB, bias, out);            // final v
}

// round 3
// speedup vs baseline: 2.1486x; 1.5541x over previous
#include <cuda_runtime.h>
#include <cuda_fp16.h>

#define BB   256
#define NN   1152
#define OO   10
#define JJ   160              // OO * 16
#define WW   80               // JJ/2 half2 words per (b,n); w = o*8 + k/2
#define EPSF 1e-7f
#define NPART 8
#define NPERW 18              // 1152 / (NPART*8 warps)

// ---- scratch (static device globals; no allocation) ----
__device__ __half2 g_uh[(size_t)BB * NN * WW];     // 94.5 MB, [b][n][w]
__device__ float   g_part[144 * BB * JJ];          // 23.6 MB uhat partials [nblk][b][j]
__device__ float   g_s0[BB * JJ];
__device__ float   g_sA[BB * JJ];
__device__ float   g_sB[BB * JJ];
__device__ float   g_v[BB * JJ];
__device__ float   g_b1[(size_t)BB * NN * OO];     // 11.8 MB logits after iter-0

// ---------------------------------------------------------------------------
__global__ void k_zero() {
    int i = blockIdx.x * blockDim.x + threadIdx.x;
    if (i < BB * JJ) { g_s0[i] = 0.f; g_sA[i] = 0.f; g_sB[i] = 0.f; }
}

// ---------------------------------------------------------------------------
// u_hat (fp32 compute, fp16 store) + iter-0 partials.  grid (144, 8),
// block 160 (thread = j).  W in regs (64/thread), x broadcast from smem.
__global__ void __launch_bounds__(160) k_uhat(const float* __restrict__ x,
                                              const float* __restrict__ w) {
    const int j  = threadIdx.x;
    const int n0 = blockIdx.x * 8;
    const int b0 = blockIdx.y * 32;

    __shared__ __align__(16) float x_sm[32 * 64];
    for (int idx = j; idx < 32 * 64; idx += 160) {
        int bb = idx >> 6, q = idx & 63;
        x_sm[idx] = x[(size_t)(b0 + bb) * (NN * 8) + n0 * 8 + q];
    }

    float Wr[8][8];
    {
        const int wb = (j >> 4) * 128 + (j & 15);   // o*128 + k
        #pragma unroll
        for (int n = 0; n < 8; n++)
            #pragma unroll
            for (int i = 0; i < 8; i++)
                Wr[n][i] = w[(size_t)(n0 + n) * 1280 + wb + i * 16];
    }
    __syncthreads();

    __half* gh = (__half*)g_uh;
    for (int bb = 0; bb < 32; bb++) {
        float acc = 0.f;
        __half* outp = &gh[((size_t)(b0 + bb) * NN + n0) * JJ + j];
        #pragma unroll
        for (int n = 0; n < 8; n++) {
            const float4* xv = reinterpret_cast<const float4*>(&x_sm[bb * 64 + n * 8]);
            float4 xa = xv[0], xb = xv[1];
            float u = Wr[n][0] * xa.x + Wr[n][1] * xa.y + Wr[n][2] * xa.z + Wr[n][3] * xa.w
                    + Wr[n][4] * xb.x + Wr[n][5] * xb.y + Wr[n][6] * xb.z + Wr[n][7] * xb.w;
            outp[n * JJ] = __float2half(u);
            acc += u;
        }
        g_part[((size_t)blockIdx.x * BB + (b0 + bb)) * JJ + j] = acc;
    }
}

// ---------------------------------------------------------------------------
// parallel reduce of uhat partials: grid (256, 8), block 160.
__global__ void k_red0() {
    const int b = blockIdx.x, j = threadIdx.x;
    const int nb0 = blockIdx.y * 18;
    float s = 0.f;
    #pragma unroll 6
    for (int nb = nb0; nb < nb0 + 18; nb++)
        s += g_part[((size_t)nb * BB + b) * JJ + j];
    atomicAdd(&g_s0[b * JJ + j], s);
}

// ---------------------------------------------------------------------------
// squash: dst = squash(scale*s + bias).  grid 256, block 160.
__global__ void k_squash(const float* __restrict__ sbuf, float scale,
                         const float* __restrict__ bias, float* __restrict__ dst) {
    const int b = blockIdx.x, j = threadIdx.x;
    float s = scale * sbuf[b * JJ + j] + bias[j];
    float d = s * s;
    #pragma unroll
    for (int msk = 1; msk < 16; msk <<= 1)
        d += __shfl_xor_sync(0xffffffffu, d, msk, 16);
    dst[b * JJ + j] = s * (d / ((1.f + d) * sqrtf(d + EPSF)));
}

// ---------------------------------------------------------------------------
// Routing iteration.  grid (256 b, NPART), block 256 (8 warps, NPERW n each).
// Lane l holds half2 words w = l + 32m (m=0,1,2; m=2 only l<16); o = 4m + (l>>3).
template <int LAST>
__global__ void __launch_bounds__(256) k_route(float* __restrict__ sbuf) {
    const int b   = blockIdx.x;
    const int tid = threadIdx.x;
    const int wp  = tid >> 5, l = tid & 31;
    const unsigned FULL = 0xffffffffu;
    const bool lo16 = (l < 16);

    const float2* vp = (const float2*)g_v + b * WW;
    float2 v0 = vp[l], v1 = vp[l + 32];
    float2 v2 = lo16 ? vp[l + 64] : make_float2(0.f, 0.f);
    float2 s0 = {0.f, 0.f}, s1 = {0.f, 0.f}, s2 = {0.f, 0.f};

    const __half2* up = g_uh + (size_t)b * NN * WW;
    const int nbeg = (blockIdx.y * 8 + wp) * NPERW;

    #pragma unroll 2
    for (int nn = 0; nn < NPERW; nn++) {
        const int n = nbeg + nn;
        const __half2* u = up + (size_t)n * WW;
        __half2 h0 = u[l], h1 = u[l + 32];
        __half2 h2 = lo16 ? u[l + 64] : __half2(__float2half(0.f), __float2half(0.f));
        float2 u0 = __half22float2(h0), u1 = __half22float2(h1), u2 = __half22float2(h2);

        float d0 = fmaf(u0.x, v0.x, u0.y * v0.y);
        float d1 = fmaf(u1.x, v1.x, u1.y * v1.y);
        float d2 = fmaf(u2.x, v2.x, u2.y * v2.y);
        #pragma unroll
        for (int msk = 1; msk < 8; msk <<= 1) {
            d0 += __shfl_xor_sync(FULL, d0, msk);
            d1 += __shfl_xor_sync(FULL, d1, msk);
            d2 += __shfl_xor_sync(FULL, d2, msk);
        }
        // gather the 10 o-dots onto lanes 0..9 (lane l == o)
        const int src = (l & 3) << 3;
        float ga = __shfl_sync(FULL, d0, src);
        float gb = __shfl_sync(FULL, d1, src);
        float gc = __shfl_sync(FULL, d2, src);
        float sel = (l < 4) ? ga : ((l < 8) ? gb : gc);

        float bn = sel;
        if (LAST) {
            if (l < 10) bn += g_b1[((size_t)b * NN + n) * OO + l];
        } else {
            if (l < 10) g_b1[((size_t)b * NN + n) * OO + l] = bn;
        }
        float e = (l < 10) ? __expf(bn) : 0.f;
        float tot = e;
        #pragma unroll
        for (int msk = 1; msk < 16; msk <<= 1)
            tot += __shfl_xor_sync(FULL, tot, msk, 16);
        float cn = __fdividef(e, tot);
        // scatter c back to the (m, 8-lane-group) slots
        const int g = l >> 3;
        float c0 = __shfl_sync(FULL, cn, g);
        float c1 = __shfl_sync(FULL, cn, 4 + g);
        float c2 = __shfl_sync(FULL, cn, 8 + g);   // garbage for l>=16; u2==0 there
        s0.x = fmaf(c0, u0.x, s0.x); s0.y = fmaf(c0, u0.y, s0.y);
        s1.x = fmaf(c1, u1.x, s1.x); s1.y = fmaf(c1, u1.y, s1.y);
        s2.x = fmaf(c2, u2.x, s2.x); s2.y = fmaf(c2, u2.y, s2.y);
    }

    __shared__ float2 ssm[8][WW];     // float view == j order
    ssm[wp][l] = s0;
    ssm[wp][l + 32] = s1;
    if (lo16) ssm[wp][l + 64] = s2;
    __syncthreads();

    if (tid < JJ) {
        const float* sf = (const float*)ssm;
        float s = 0.f;
        #pragma unroll
        for (int w8 = 0; w8 < 8; w8++) s += sf[w8 * JJ + tid];
        atomicAdd(&sbuf[b * JJ + tid], s);
    }
}

// ---------------------------------------------------------------------------
extern "C" void kernel_launch(void* const* d_in, const int* in_sizes, int n_in,
                              void* d_out, int out_size) {
    const float* x    = (const float*)d_in[0];
    const float* w    = (const float*)d_in[1];
    const float* bias = (const float*)d_in[2];
    float* out = (float*)d_out;

    float* s0; cudaGetSymbolAddress((void**)&s0, g_s0);
    float* sA; cudaGetSymbolAddress((void**)&sA, g_sA);
    float* sB; cudaGetSymbolAddress((void**)&sB, g_sB);
    float* v;  cudaGetSymbolAddress((void**)&v,  g_v);

    k_zero<<<40, 1024>>>();
    k_uhat<<<dim3(144, 8), 160>>>(x, w);
    k_red0<<<dim3(256, 8), 160>>>();
    k_squash<<<256, 160>>>(s0, 0.1f, bias, v);        // v0
    k_route<0><<<dim3(256, NPART), 256>>>(sA);        // iter 1 partials + b1
    k_squash<<<256, 160>>>(sA, 1.0f, bias, v);        // v1
    k_route<1><<<dim3(256, NPART), 256>>>(sB);        // iter 2 partials
    k_squash<<<256, 160>>>(sB, 1.0f, bias, out);      // final
}